// round 11
// baseline (speedup 1.0000x reference)
#include <cuda_runtime.h>
#include <cuda_bf16.h>
#include <cstdint>

#define V_SIZE 50257
#define NT64   786
#define NP     50304
#define NGRP   9
#define KDIM   768
#define MROWS  2048
#define HD     769
#define LOG_V  10.8249046870f
#define LOG2E  1.44269504089f
#define PADC   17.2903373075f   // 47 * exp(-1): padded-col correction to S1

#if defined(__CUDA_ARCH__) && (defined(__CUDA_ARCH_FEAT_SM103_ALL) || \
    defined(__CUDA_ARCH_FEAT_SM100_ALL) || defined(__CUDA_ARCH_SPECIFIC__) || \
    defined(__CUDA_ARCH_FAMILY_SPECIFIC__))
#define USE_TCGEN05 1
#else
#define USE_TCGEN05 0
#endif

#define SLAB     8192          // one k-chunk: 64 rows x 128B
#define BIG      32768         // bulk unit: 4 k-chunks
#define NSLOT    5             // big-slab ring slots (160 KB)
#define PBYTES   32768         // one P buffer: 128x64 fp32
#define DYN_SMEM (1024 + NSLOT * BIG + 2 * PBYTES)   // 230400 B
#define NTHREADS 800           // 1 producer + 8 loader + 16 epilogue warps

// g_Wn: pre-swizzled TILE-MAJOR: slab (nt,kt) = contiguous 8KB at (nt*12+kt)*8192
__device__ __align__(16) __nv_bfloat16 g_Wn[(size_t)NP * KDIM];
__device__ __align__(16) __nv_bfloat16 g_Un[(size_t)MROWS * KDIM];
__device__ __align__(16) uint32_t g_UnT[16 * 384 * 128];   // [mt][col][row] u32
__device__ float g_rs[MROWS];
__device__ float g_S1[MROWS];
__device__ float g_S2[MROWS];
__device__ float g_S3[MROWS];

__global__ __launch_bounds__(256) void prep_w_kernel(const float* __restrict__ W) {
    const int warp = threadIdx.x >> 5, lane = threadIdx.x & 31;
    const int v = blockIdx.x * 8 + warp;
    const int nt = v >> 6, row = v & 63;
    float f[24]; float ss = 1.f;
    if (v < V_SIZE) {
        const float* rp = W + (size_t)v * HD + 1;
        ss = 0.f;
        #pragma unroll
        for (int j = 0; j < 24; ++j) { f[j] = rp[lane + j * 32]; ss = fmaf(f[j], f[j], ss); }
        #pragma unroll
        for (int o = 16; o > 0; o >>= 1) ss += __shfl_xor_sync(0xffffffffu, ss, o);
    } else {
        #pragma unroll
        for (int j = 0; j < 24; ++j) f[j] = 0.f;
    }
    const float inv = rsqrtf(fmaxf(ss, 1e-24f));
    char* const base = (char*)g_Wn;
    #pragma unroll
    for (int j = 0; j < 24; ++j) {
        const int k = lane + j * 32;
        const int kt = k >> 6, e = k & 63;
        const uint32_t off = (uint32_t)(row * 128 + e * 2);
        const uint32_t sw  = off ^ ((off >> 3) & 0x70u);
        *(__nv_bfloat16*)(base + (size_t)(nt * 12 + kt) * SLAB + sw) =
            __float2bfloat16(f[j] * inv);
    }
}

__global__ __launch_bounds__(256) void prep_s_kernel(const float* __restrict__ H) {
    const int warp = threadIdx.x >> 5, lane = threadIdx.x & 31;
    const int m = blockIdx.x * 8 + warp;
    const float* row = H + (size_t)m * HD + 1;
    float f[24]; float ss = 0.f;
    #pragma unroll
    for (int j = 0; j < 24; ++j) { f[j] = row[lane + j * 32]; ss = fmaf(f[j], f[j], ss); }
    #pragma unroll
    for (int o = 16; o > 0; o >>= 1) ss += __shfl_xor_sync(0xffffffffu, ss, o);
    if (lane == 0) {
        float x0 = fmaxf(H[(size_t)m * HD], 1.f + 1e-7f);
        g_rs[m] = acoshf(x0);
        g_S1[m] = 0.f; g_S2[m] = 0.f; g_S3[m] = 0.f;
    }
    const float inv = rsqrtf(fmaxf(ss, 1e-24f));
    __nv_bfloat16* dst = g_Un + (size_t)m * KDIM;
    #pragma unroll
    for (int j = 0; j < 24; ++j) dst[lane + j * 32] = __float2bfloat16(f[j] * inv);
}

__global__ __launch_bounds__(128) void transpose_a_kernel() {
    const int mt = blockIdx.x, cc = blockIdx.y;
    const int lane = threadIdx.x & 31, w = threadIdx.x >> 5;
    const uint32_t* src = (const uint32_t*)g_Un;
    #pragma unroll
    for (int it = 0; it < 32; ++it) {
        const int r = w * 32 + it;
        g_UnT[((size_t)mt * 384 + cc * 32 + lane) * 128 + r] =
            src[(size_t)(mt * 128 + r) * 384 + cc * 32 + lane];
    }
}

extern __shared__ char dynsm[];

#if USE_TCGEN05
__device__ __forceinline__ uint32_t elect_one() {
    uint32_t p;
    asm volatile("{\n\t.reg .pred p;\n\telect.sync _|p, 0xFFFFFFFF;\n\t"
                 "selp.b32 %0, 1, 0, p;\n\t}" : "=r"(p));
    return p;
}
__device__ __forceinline__ void mbar_wait(uint32_t addr, uint32_t parity) {
    asm volatile(
        "{\n\t.reg .pred P1;\n\t"
        "WAIT_LOOP_%=:\n\t"
        "mbarrier.try_wait.parity.acquire.cta.shared::cta.b64 P1, [%0], %1, 0x989680;\n\t"
        "@P1 bra.uni WAIT_DONE_%=;\n\t"
        "bra.uni WAIT_LOOP_%=;\n\t"
        "WAIT_DONE_%=:\n\t}"
        :: "r"(addr), "r"(parity) : "memory");
}
__device__ __forceinline__ void mbar_arrive(uint32_t addr) {
    asm volatile("mbarrier.arrive.shared.b64 _, [%0];" :: "r"(addr) : "memory");
}
__device__ __forceinline__ void bulk_ld(uint32_t dst, const void* src, uint32_t mbar) {
    asm volatile(
        "cp.async.bulk.shared::cluster.global.mbarrier::complete_tx::bytes "
        "[%0], [%1], %2, [%3];"
        :: "r"(dst), "l"(src), "r"((uint32_t)BIG), "r"(mbar) : "memory");
}
#endif

__global__ __launch_bounds__(NTHREADS, 1) void gemm_fused_kernel(const float* __restrict__ P) {
    const int tid = threadIdx.x, lane = tid & 31, warp = tid >> 5;
    const int mt = blockIdx.x, grp = blockIdx.y;
    const int ntc = (NT64 - 1 - grp) / NGRP + 1;

#if USE_TCGEN05
    __shared__ __align__(8) unsigned long long m_full[NSLOT];
    __shared__ __align__(8) unsigned long long m_empty[NSLOT];
    __shared__ __align__(8) unsigned long long m_tdone[2];
    __shared__ __align__(8) unsigned long long m_dfree[2];
    __shared__ __align__(8) unsigned long long m_pready[2];
    __shared__ __align__(8) unsigned long long m_pfree[2];
    __shared__ uint32_t tptr_s[1];

    const uint32_t smraw = (uint32_t)__cvta_generic_to_shared(dynsm);
    const uint32_t smB   = (smraw + 1023u) & ~1023u;
    float* const Psm0    = (float*)(dynsm + (smB - smraw) + NSLOT * BIG);
    const uint32_t FULL   = (uint32_t)__cvta_generic_to_shared(m_full);
    const uint32_t EMPTY  = (uint32_t)__cvta_generic_to_shared(m_empty);
    const uint32_t TDONE  = (uint32_t)__cvta_generic_to_shared(m_tdone);
    const uint32_t DFREE  = (uint32_t)__cvta_generic_to_shared(m_dfree);
    const uint32_t PREADY = (uint32_t)__cvta_generic_to_shared(m_pready);
    const uint32_t PFREE  = (uint32_t)__cvta_generic_to_shared(m_pfree);
    const uint32_t tptr   = (uint32_t)__cvta_generic_to_shared(tptr_s);

    if (warp == 0) {
        asm volatile("tcgen05.alloc.cta_group::1.sync.aligned.shared::cta.b32 [%0], %1;"
                     :: "r"(tptr), "r"(512u) : "memory");
        asm volatile("tcgen05.relinquish_alloc_permit.cta_group::1.sync.aligned;");
    }
    if (tid == 0) {
        #pragma unroll
        for (int s = 0; s < NSLOT; ++s) {
            asm volatile("mbarrier.init.shared.b64 [%0], 1;" :: "r"(FULL + s * 8) : "memory");
            asm volatile("mbarrier.init.shared.b64 [%0], 1;" :: "r"(EMPTY + s * 8) : "memory");
        }
        #pragma unroll
        for (int b = 0; b < 2; ++b) {
            asm volatile("mbarrier.init.shared.b64 [%0], 1;"  :: "r"(TDONE + b * 8) : "memory");
            asm volatile("mbarrier.init.shared.b64 [%0], 16;" :: "r"(DFREE + b * 8) : "memory");
            asm volatile("mbarrier.init.shared.b64 [%0], 1;"  :: "r"(PREADY + b * 8) : "memory");
            asm volatile("mbarrier.init.shared.b64 [%0], 16;" :: "r"(PFREE + b * 8) : "memory");
        }
    }
    __syncthreads();
    uint32_t tmem;
    asm volatile("ld.shared.b32 %0, [%1];" : "=r"(tmem) : "r"(tptr));

    // ---- stage A (128x768 bf16) into TMEM cols 128..511 (warps 0-3, once) ----
    if (warp < 4) {
        const uint32_t woff = ((uint32_t)warp) << 21;
        #pragma unroll 1
        for (int c = 0; c < 12; ++c) {
            uint32_t a[32];
            const uint32_t* src = g_UnT + ((size_t)mt * 384 + c * 32) * 128 + warp * 32 + lane;
            #pragma unroll
            for (int i = 0; i < 32; ++i) a[i] = src[(size_t)i * 128];
            const uint32_t ta = tmem + 128u + (uint32_t)(c * 32) + woff;
            asm volatile(
                "tcgen05.st.sync.aligned.32x32b.x32.b32 [%0], "
                "{%1,%2,%3,%4,%5,%6,%7,%8,%9,%10,%11,%12,%13,%14,%15,%16,"
                "%17,%18,%19,%20,%21,%22,%23,%24,%25,%26,%27,%28,%29,%30,%31,%32};"
                :: "r"(ta),
                   "r"(a[0]),  "r"(a[1]),  "r"(a[2]),  "r"(a[3]),
                   "r"(a[4]),  "r"(a[5]),  "r"(a[6]),  "r"(a[7]),
                   "r"(a[8]),  "r"(a[9]),  "r"(a[10]), "r"(a[11]),
                   "r"(a[12]), "r"(a[13]), "r"(a[14]), "r"(a[15]),
                   "r"(a[16]), "r"(a[17]), "r"(a[18]), "r"(a[19]),
                   "r"(a[20]), "r"(a[21]), "r"(a[22]), "r"(a[23]),
                   "r"(a[24]), "r"(a[25]), "r"(a[26]), "r"(a[27]),
                   "r"(a[28]), "r"(a[29]), "r"(a[30]), "r"(a[31])
                : "memory");
        }
        asm volatile("tcgen05.wait::st.sync.aligned;" ::: "memory");
    }
    asm volatile("tcgen05.fence::before_thread_sync;" ::: "memory");
    __syncthreads();

    const int total = ntc * 3;           // big slabs
    const uint32_t IDESC = (1u << 4) | (1u << 7) | (1u << 10) | (8u << 17) | (8u << 24);
    const uint64_t DESC_BASE = (2ull << 61) | (1ull << 46) | (64ull << 32) | (1ull << 16);

    if (warp == 0) {
        // =================== producer / MMA warp ===================
        asm volatile("tcgen05.fence::after_thread_sync;" ::: "memory");
        const char* const WB = (const char*)g_Wn;
        auto slab_src = [&](int s) -> const void* {
            const int j = s / 3, b3 = s - j * 3;
            const int nt = grp + NGRP * j;
            return WB + ((size_t)(nt * 12) + b3 * 4) * SLAB;
        };
        if (elect_one()) {
            #pragma unroll 1
            for (int s = 0; s < NSLOT && s < total; ++s) {
                asm volatile("mbarrier.arrive.expect_tx.shared.b64 _, [%0], %1;"
                             :: "r"(FULL + s * 8), "r"((uint32_t)BIG) : "memory");
                bulk_ld(smB + s * BIG, slab_src(s), FULL + s * 8);
            }
        }
        __syncwarp();

        uint32_t fmask = 0, emask = 0;
        int dfph = 0;
        #pragma unroll 1
        for (int ub = 0; ub < total; ++ub) {
            const int j = ub / 3, b3 = ub - j * 3, slot = ub % NSLOT, db = j & 1;
            if (ub >= 2 && (ub + 3) < total) {
                const int sp = (ub - 2) % NSLOT;
                mbar_wait(EMPTY + sp * 8, (emask >> sp) & 1u); emask ^= 1u << sp;
                if (elect_one()) {
                    asm volatile("mbarrier.arrive.expect_tx.shared.b64 _, [%0], %1;"
                                 :: "r"(FULL + sp * 8), "r"((uint32_t)BIG) : "memory");
                    bulk_ld(smB + sp * BIG, slab_src(ub + 3), FULL + sp * 8);
                }
                __syncwarp();
            }
            if (b3 == 0 && j >= 2) {
                mbar_wait(DFREE + db * 8, (uint32_t)((dfph >> db) & 1)); dfph ^= 1 << db;
            }
            mbar_wait(FULL + slot * 8, (fmask >> slot) & 1u); fmask ^= 1u << slot;
            if (elect_one()) {
                const uint32_t dcol = tmem + (uint32_t)(db * 64);
                #pragma unroll
                for (int c = 0; c < 4; ++c) {
                    const uint64_t bd = DESC_BASE |
                        (((smB + slot * BIG + c * SLAB) >> 4) & 0x3FFFu);
                    const int kg = b3 * 4 + c;
                    #pragma unroll
                    for (int kk = 0; kk < 4; ++kk) {
                        const uint32_t en = (kg > 0 || kk > 0) ? 1u : 0u;
                        const uint32_t at = tmem + 128u + (uint32_t)(kg * 32 + kk * 8);
                        asm volatile(
                            "{\n\t.reg .pred p;\n\tsetp.ne.u32 p, %4, 0;\n\t"
                            "tcgen05.mma.cta_group::1.kind::f16 [%0], [%1], %2, %3, "
                            "{%5,%5,%5,%5}, p;\n\t}"
                            :: "r"(dcol), "r"(at), "l"(bd + kk * 2),
                               "r"(IDESC), "r"(en), "r"(0u) : "memory");
                    }
                }
                asm volatile(
                    "tcgen05.commit.cta_group::1.mbarrier::arrive::one.shared::cluster.b64 [%0];"
                    :: "r"(EMPTY + slot * 8) : "memory");
                if (b3 == 2)
                    asm volatile(
                        "tcgen05.commit.cta_group::1.mbarrier::arrive::one.shared::cluster.b64 [%0];"
                        :: "r"(TDONE + db * 8) : "memory");
            }
            __syncwarp();
        }
        #pragma unroll 1
        for (int j = (ntc >= 2 ? ntc - 2 : 0); j < ntc; ++j) {
            const int db = j & 1;
            mbar_wait(DFREE + db * 8, (uint32_t)((dfph >> db) & 1)); dfph ^= 1 << db;
        }
        asm volatile("tcgen05.dealloc.cta_group::1.sync.aligned.b32 %0, %1;"
                     :: "r"(tmem), "r"(512u));
    } else if (warp <= 8) {
        // =================== P-loader warps (1..8) ===================
        const int lt = tid - 32;              // 0..255
        int pf0 = 0, pf1 = 0;
        #pragma unroll 1
        for (int j = 0; j < ntc; ++j) {
            const int b = j & 1;
            if (j >= 2) {
                if (b == 0) { mbar_wait(PFREE,     (uint32_t)pf0); pf0 ^= 1; }
                else        { mbar_wait(PFREE + 8, (uint32_t)pf1); pf1 ^= 1; }
            }
            float* const buf = Psm0 + (b << 13);
            const int vb = (grp + NGRP * j) * 64;
            #pragma unroll
            for (int i = 0; i < 32; ++i) {
                const int idx = lt + i * 256;
                const int row = idx >> 6, col = idx & 63;
                const int v = vb + col;
                const float val = (v < V_SIZE)
                    ? __ldg(P + (size_t)(mt * 128 + row) * V_SIZE + v) : 0.f;
                buf[(row << 6) + (((col >> 2) ^ (row & 15)) << 2) + (col & 3)] = val;
            }
            asm volatile("bar.sync 2, 256;" ::: "memory");   // drains STS
            if (tid == 32) mbar_arrive(PREADY + b * 8);
        }
    } else {
        // =================== epilogue warps (9..24) ===================
        const int e    = warp - 9;             // 0..15 (warp base ≡ 1 mod 4, as R10)
        const int sub  = e & 3;
        const int chb  = (e >> 2) * 16;        // column quarter within 64-col D
        const int lrow = sub * 32 + lane;
        const int rg   = mt * 128 + lrow;
        int tdph0 = 0, tdph1 = 0, pr0 = 0, pr1 = 0;
        float s1 = 0.f, s2 = 0.f, s3 = 0.f;

        #pragma unroll 1
        for (int j = 0; j < ntc; ++j) {
            const int b = j & 1;
            if (b == 0) { mbar_wait(PREADY,     (uint32_t)pr0); pr0 ^= 1;
                          mbar_wait(TDONE,      (uint32_t)tdph0); tdph0 ^= 1; }
            else        { mbar_wait(PREADY + 8, (uint32_t)pr1); pr1 ^= 1;
                          mbar_wait(TDONE + 8,  (uint32_t)tdph1); tdph1 ^= 1; }
            asm volatile("tcgen05.fence::after_thread_sync;" ::: "memory");

            uint32_t d[16];
            const uint32_t ta = tmem + (uint32_t)(b * 64 + chb);
            asm volatile(
                "tcgen05.ld.sync.aligned.32x32b.x16.b32 "
                "{%0,%1,%2,%3,%4,%5,%6,%7,%8,%9,%10,%11,%12,%13,%14,%15}, [%16];"
                : "=r"(d[0]),  "=r"(d[1]),  "=r"(d[2]),  "=r"(d[3]),
                  "=r"(d[4]),  "=r"(d[5]),  "=r"(d[6]),  "=r"(d[7]),
                  "=r"(d[8]),  "=r"(d[9]),  "=r"(d[10]), "=r"(d[11]),
                  "=r"(d[12]), "=r"(d[13]), "=r"(d[14]), "=r"(d[15])
                : "r"(ta));
            asm volatile("tcgen05.wait::ld.sync.aligned;" ::: "memory");
            if (lane == 0) mbar_arrive(DFREE + b * 8);

            const float4* Psm4 = (const float4*)(Psm0 + (b << 13));
            #pragma unroll
            for (int ii = 0; ii < 4; ++ii) {
                const int c4 = (chb >> 2) + ii;
                const float4 p4 = Psm4[(lrow << 4) + (c4 ^ (lrow & 15))];
                const float pv[4] = {p4.x, p4.y, p4.z, p4.w};
                #pragma unroll
                for (int ee = 0; ee < 4; ++ee) {
                    const float lg = __uint_as_float(d[ii * 4 + ee]);
                    s1 += exp2f(fmaf(lg, LOG2E, -LOG2E));
                    s2 = fmaf(pv[ee], lg, s2);
                    s3 = fmaf(pv[ee], __logf(fmaxf(pv[ee], 1e-12f)), s3);
                }
            }
            if (lane == 0) mbar_arrive(PFREE + b * 8);
        }
        atomicAdd(&g_S1[rg], s1);
        atomicAdd(&g_S2[rg], s2);
        atomicAdd(&g_S3[rg], s3);
    }
#else
    // Dead-code fallback (sm_103a cubin is always selected at runtime).
    for (int j = 0; j < ntc; ++j) {
        const int nt = grp + NGRP * j;
        for (int idx = tid; idx < 64 * 128; idx += NTHREADS) {
            const int row = idx >> 6, col = idx & 63;
            const int v = nt * 64 + col;
            if (v >= V_SIZE) continue;
            const int r = mt * 128 + row;
            float lg = 0.f;
            const __nv_bfloat16* ua = g_Un + (size_t)r * KDIM;
            const char* base = (const char*)g_Wn;
            for (int k = 0; k < KDIM; ++k) {
                const int kt = k >> 6, ek = k & 63;
                const uint32_t off = (uint32_t)(col * 128 + ek * 2);
                const uint32_t sw  = off ^ ((off >> 3) & 0x70u);
                const __nv_bfloat16 wb =
                    *(const __nv_bfloat16*)(base + (size_t)(nt * 12 + kt) * SLAB + sw);
                lg = fmaf(__bfloat162float(ua[k]), __bfloat162float(wb), lg);
            }
            const float p = __ldg(P + (size_t)r * V_SIZE + v);
            atomicAdd(&g_S1[r], exp2f(fmaf(lg, LOG2E, -LOG2E)) + PADC / 128.f);
            atomicAdd(&g_S2[r], p * lg);
            atomicAdd(&g_S3[r], p * __logf(fmaxf(p, 1e-12f)));
        }
    }
#endif
}

__global__ __launch_bounds__(1024) void finalize_kernel(const float* __restrict__ TE,
                                                        float* __restrict__ out) {
    const int t = threadIdx.x;
    float v0 = 0.f, v1 = 0.f, v2 = 0.f, v3 = 0.f, v4 = 0.f;
    for (int r = t; r < MROWS; r += 1024) {
        v0 += g_S3[r] - g_S2[r] + 1.f + __logf(g_S1[r] - PADC);  // remove padded cols
        float rr = g_rs[r];
        v1 += rr;
        float Hn = fminf(fmaxf(TE[r] * (1.f / LOG_V), 0.f), 1.f);
        float rtg = 3.0f / (1.f + expf(Hn));
        float d = rr - rtg;
        v2 = fmaf(d, d, v2);
        v3 += rtg;
        v4 += Hn;
    }
    #pragma unroll
    for (int o = 16; o > 0; o >>= 1) {
        v0 += __shfl_xor_sync(0xffffffffu, v0, o);
        v1 += __shfl_xor_sync(0xffffffffu, v1, o);
        v2 += __shfl_xor_sync(0xffffffffu, v2, o);
        v3 += __shfl_xor_sync(0xffffffffu, v3, o);
        v4 += __shfl_xor_sync(0xffffffffu, v4, o);
    }
    __shared__ float sb[32][5];
    if ((t & 31) == 0) {
        int w = t >> 5;
        sb[w][0] = v0; sb[w][1] = v1; sb[w][2] = v2; sb[w][3] = v3; sb[w][4] = v4;
    }
    __syncthreads();
    if (t < 32) {
        float u0 = sb[t][0], u1 = sb[t][1], u2 = sb[t][2], u3 = sb[t][3], u4 = sb[t][4];
        #pragma unroll
        for (int o = 16; o > 0; o >>= 1) {
            u0 += __shfl_xor_sync(0xffffffffu, u0, o);
            u1 += __shfl_xor_sync(0xffffffffu, u1, o);
            u2 += __shfl_xor_sync(0xffffffffu, u2, o);
            u3 += __shfl_xor_sync(0xffffffffu, u3, o);
            u4 += __shfl_xor_sync(0xffffffffu, u4, o);
        }
        if (t == 0) {
            const float inv = 1.f / (float)MROWS;
            float l_ang = u0 * inv;
            float l_rad = u2 * inv;
            out[0] = l_ang + 0.1f * l_rad;
            out[1] = l_ang;
            out[2] = l_rad;
            out[3] = u1 * inv;
            out[4] = u3 * inv;
            out[5] = u4 * inv;
        }
    }
}

extern "C" void kernel_launch(void* const* d_in, const int* in_sizes, int n_in,
                              void* d_out, int out_size) {
    const float* h  = (const float*)d_in[0];
    const float* W  = (const float*)d_in[1];
    const float* P  = (const float*)d_in[2];
    const float* TE = (const float*)d_in[3];
    float* out = (float*)d_out;

    cudaFuncSetAttribute(gemm_fused_kernel,
                         cudaFuncAttributeMaxDynamicSharedMemorySize, DYN_SMEM);

    prep_w_kernel<<<NP / 8, 256>>>(W);
    prep_s_kernel<<<MROWS / 8, 256>>>(h);
    transpose_a_kernel<<<dim3(16, 12), 128>>>();
    gemm_fused_kernel<<<dim3(16, NGRP), NTHREADS, DYN_SMEM>>>(P);
    finalize_kernel<<<1, 1024>>>(TE, out);
}

// round 12
// speedup vs baseline: 1.7432x; 1.7432x over previous
#include <cuda_runtime.h>
#include <cuda_bf16.h>
#include <cstdint>

#define V_SIZE 50257
#define NT64   786
#define NP     50304
#define NGRP   9
#define KDIM   768
#define MROWS  2048
#define HD     769
#define LOG_V  10.8249046870f
#define LOG2E  1.44269504089f
#define PADC   17.2903373075f   // 47 * exp(-1): padded-col correction to S1

#if defined(__CUDA_ARCH__) && (defined(__CUDA_ARCH_FEAT_SM103_ALL) || \
    defined(__CUDA_ARCH_FEAT_SM100_ALL) || defined(__CUDA_ARCH_SPECIFIC__) || \
    defined(__CUDA_ARCH_FAMILY_SPECIFIC__))
#define USE_TCGEN05 1
#else
#define USE_TCGEN05 0
#endif

#define SLAB     8192          // one k-chunk: 64 rows x 128B
#define BIG      32768         // bulk unit: 4 k-chunks
#define NSLOT    4             // big-slab ring slots (128 KB)
#define PBYTES   32768         // one P buffer: 128x64 fp32
#define DYN_SMEM (1024 + NSLOT * BIG + 2 * PBYTES)
#define NTHREADS 544           // 1 producer warp + 16 epilogue warps (2 groups of 8)

// g_Wn: pre-swizzled TILE-MAJOR: slab (nt,kt) = contiguous 8KB at (nt*12+kt)*8192
__device__ __align__(16) __nv_bfloat16 g_Wn[(size_t)NP * KDIM];
__device__ __align__(16) __nv_bfloat16 g_Un[(size_t)MROWS * KDIM];
__device__ __align__(16) uint32_t g_UnT[16 * 384 * 128];   // [mt][col][row] u32
__device__ float g_rs[MROWS];
__device__ float g_S1[MROWS];
__device__ float g_S2[MROWS];
__device__ float g_S3[MROWS];

__global__ __launch_bounds__(256) void prep_w_kernel(const float* __restrict__ W) {
    const int warp = threadIdx.x >> 5, lane = threadIdx.x & 31;
    const int v = blockIdx.x * 8 + warp;
    const int nt = v >> 6, row = v & 63;
    float f[24]; float ss = 1.f;
    if (v < V_SIZE) {
        const float* rp = W + (size_t)v * HD + 1;
        ss = 0.f;
        #pragma unroll
        for (int j = 0; j < 24; ++j) { f[j] = rp[lane + j * 32]; ss = fmaf(f[j], f[j], ss); }
        #pragma unroll
        for (int o = 16; o > 0; o >>= 1) ss += __shfl_xor_sync(0xffffffffu, ss, o);
    } else {
        #pragma unroll
        for (int j = 0; j < 24; ++j) f[j] = 0.f;
    }
    const float inv = rsqrtf(fmaxf(ss, 1e-24f));
    char* const base = (char*)g_Wn;
    #pragma unroll
    for (int j = 0; j < 24; ++j) {
        const int k = lane + j * 32;
        const int kt = k >> 6, e = k & 63;
        const uint32_t off = (uint32_t)(row * 128 + e * 2);
        const uint32_t sw  = off ^ ((off >> 3) & 0x70u);
        *(__nv_bfloat16*)(base + (size_t)(nt * 12 + kt) * SLAB + sw) =
            __float2bfloat16(f[j] * inv);
    }
}

__global__ __launch_bounds__(256) void prep_s_kernel(const float* __restrict__ H) {
    const int warp = threadIdx.x >> 5, lane = threadIdx.x & 31;
    const int m = blockIdx.x * 8 + warp;
    const float* row = H + (size_t)m * HD + 1;
    float f[24]; float ss = 0.f;
    #pragma unroll
    for (int j = 0; j < 24; ++j) { f[j] = row[lane + j * 32]; ss = fmaf(f[j], f[j], ss); }
    #pragma unroll
    for (int o = 16; o > 0; o >>= 1) ss += __shfl_xor_sync(0xffffffffu, ss, o);
    if (lane == 0) {
        float x0 = fmaxf(H[(size_t)m * HD], 1.f + 1e-7f);
        g_rs[m] = acoshf(x0);
        g_S1[m] = 0.f; g_S2[m] = 0.f; g_S3[m] = 0.f;
    }
    const float inv = rsqrtf(fmaxf(ss, 1e-24f));
    __nv_bfloat16* dst = g_Un + (size_t)m * KDIM;
    #pragma unroll
    for (int j = 0; j < 24; ++j) dst[lane + j * 32] = __float2bfloat16(f[j] * inv);
}

__global__ __launch_bounds__(128) void transpose_a_kernel() {
    const int mt = blockIdx.x, cc = blockIdx.y;
    const int lane = threadIdx.x & 31, w = threadIdx.x >> 5;
    const uint32_t* src = (const uint32_t*)g_Un;
    #pragma unroll
    for (int it = 0; it < 32; ++it) {
        const int r = w * 32 + it;
        g_UnT[((size_t)mt * 384 + cc * 32 + lane) * 128 + r] =
            src[(size_t)(mt * 128 + r) * 384 + cc * 32 + lane];
    }
}

extern __shared__ char dynsm[];

#if USE_TCGEN05
__device__ __forceinline__ uint32_t elect_one() {
    uint32_t p;
    asm volatile("{\n\t.reg .pred p;\n\telect.sync _|p, 0xFFFFFFFF;\n\t"
                 "selp.b32 %0, 1, 0, p;\n\t}" : "=r"(p));
    return p;
}
__device__ __forceinline__ void mbar_wait(uint32_t addr, uint32_t parity) {
    asm volatile(
        "{\n\t.reg .pred P1;\n\t"
        "WAIT_LOOP_%=:\n\t"
        "mbarrier.try_wait.parity.acquire.cta.shared::cta.b64 P1, [%0], %1, 0x989680;\n\t"
        "@P1 bra.uni WAIT_DONE_%=;\n\t"
        "bra.uni WAIT_LOOP_%=;\n\t"
        "WAIT_DONE_%=:\n\t}"
        :: "r"(addr), "r"(parity) : "memory");
}
__device__ __forceinline__ void mbar_arrive(uint32_t addr) {
    asm volatile("mbarrier.arrive.shared.b64 _, [%0];" :: "r"(addr) : "memory");
}
__device__ __forceinline__ void bulk_ld(uint32_t dst, const void* src, uint32_t mbar) {
    asm volatile(
        "cp.async.bulk.shared::cluster.global.mbarrier::complete_tx::bytes "
        "[%0], [%1], %2, [%3];"
        :: "r"(dst), "l"(src), "r"((uint32_t)BIG), "r"(mbar) : "memory");
}
#endif

__global__ __launch_bounds__(NTHREADS, 1) void gemm_fused_kernel(const float* __restrict__ P) {
    const int tid = threadIdx.x, lane = tid & 31, warp = tid >> 5;
    const int mt = blockIdx.x, grp = blockIdx.y;
    const int ntc = (NT64 - 1 - grp) / NGRP + 1;

#if USE_TCGEN05
    __shared__ __align__(8) unsigned long long m_full[NSLOT];
    __shared__ __align__(8) unsigned long long m_empty[NSLOT];
    __shared__ __align__(8) unsigned long long m_tdone[2];
    __shared__ __align__(8) unsigned long long m_dfree[2];
    __shared__ uint32_t tptr_s[1];

    const uint32_t smraw = (uint32_t)__cvta_generic_to_shared(dynsm);
    const uint32_t smB   = (smraw + 1023u) & ~1023u;
    float* const Psm0    = (float*)(dynsm + (smB - smraw) + NSLOT * BIG);
    const uint32_t FULL  = (uint32_t)__cvta_generic_to_shared(m_full);
    const uint32_t EMPTY = (uint32_t)__cvta_generic_to_shared(m_empty);
    const uint32_t TDONE = (uint32_t)__cvta_generic_to_shared(m_tdone);
    const uint32_t DFREE = (uint32_t)__cvta_generic_to_shared(m_dfree);
    const uint32_t tptr  = (uint32_t)__cvta_generic_to_shared(tptr_s);

    if (warp == 0) {
        asm volatile("tcgen05.alloc.cta_group::1.sync.aligned.shared::cta.b32 [%0], %1;"
                     :: "r"(tptr), "r"(512u) : "memory");
        asm volatile("tcgen05.relinquish_alloc_permit.cta_group::1.sync.aligned;");
    }
    if (tid == 0) {
        #pragma unroll
        for (int s = 0; s < NSLOT; ++s) {
            asm volatile("mbarrier.init.shared.b64 [%0], 1;" :: "r"(FULL + s * 8) : "memory");
            asm volatile("mbarrier.init.shared.b64 [%0], 1;" :: "r"(EMPTY + s * 8) : "memory");
        }
        #pragma unroll
        for (int b = 0; b < 2; ++b) {
            asm volatile("mbarrier.init.shared.b64 [%0], 1;" :: "r"(TDONE + b * 8) : "memory");
            asm volatile("mbarrier.init.shared.b64 [%0], 8;" :: "r"(DFREE + b * 8) : "memory");
        }
    }
    __syncthreads();
    uint32_t tmem;
    asm volatile("ld.shared.b32 %0, [%1];" : "=r"(tmem) : "r"(tptr));

    // ---- stage A (128x768 bf16) into TMEM cols 128..511 (warps 0-3, once) ----
    if (warp < 4) {
        const uint32_t woff = ((uint32_t)warp) << 21;
        #pragma unroll 1
        for (int c = 0; c < 12; ++c) {
            uint32_t a[32];
            const uint32_t* src = g_UnT + ((size_t)mt * 384 + c * 32) * 128 + warp * 32 + lane;
            #pragma unroll
            for (int i = 0; i < 32; ++i) a[i] = src[(size_t)i * 128];
            const uint32_t ta = tmem + 128u + (uint32_t)(c * 32) + woff;
            asm volatile(
                "tcgen05.st.sync.aligned.32x32b.x32.b32 [%0], "
                "{%1,%2,%3,%4,%5,%6,%7,%8,%9,%10,%11,%12,%13,%14,%15,%16,"
                "%17,%18,%19,%20,%21,%22,%23,%24,%25,%26,%27,%28,%29,%30,%31,%32};"
                :: "r"(ta),
                   "r"(a[0]),  "r"(a[1]),  "r"(a[2]),  "r"(a[3]),
                   "r"(a[4]),  "r"(a[5]),  "r"(a[6]),  "r"(a[7]),
                   "r"(a[8]),  "r"(a[9]),  "r"(a[10]), "r"(a[11]),
                   "r"(a[12]), "r"(a[13]), "r"(a[14]), "r"(a[15]),
                   "r"(a[16]), "r"(a[17]), "r"(a[18]), "r"(a[19]),
                   "r"(a[20]), "r"(a[21]), "r"(a[22]), "r"(a[23]),
                   "r"(a[24]), "r"(a[25]), "r"(a[26]), "r"(a[27]),
                   "r"(a[28]), "r"(a[29]), "r"(a[30]), "r"(a[31])
                : "memory");
        }
        asm volatile("tcgen05.wait::st.sync.aligned;" ::: "memory");
    }
    asm volatile("tcgen05.fence::before_thread_sync;" ::: "memory");
    __syncthreads();

    const int total = ntc * 3;           // big slabs
    const uint32_t IDESC = (1u << 4) | (1u << 7) | (1u << 10) | (8u << 17) | (8u << 24);
    const uint64_t DESC_BASE = (2ull << 61) | (1ull << 46) | (64ull << 32) | (1ull << 16);

    if (warp == 0) {
        // =================== producer / MMA warp ===================
        asm volatile("tcgen05.fence::after_thread_sync;" ::: "memory");
        const char* const WB = (const char*)g_Wn;
        auto slab_src = [&](int s) -> const void* {
            const int j = s / 3, b3 = s - j * 3;
            const int nt = grp + NGRP * j;
            return WB + ((size_t)(nt * 12) + b3 * 4) * SLAB;
        };
        if (elect_one()) {
            #pragma unroll 1
            for (int s = 0; s < NSLOT && s < total; ++s) {
                asm volatile("mbarrier.arrive.expect_tx.shared.b64 _, [%0], %1;"
                             :: "r"(FULL + s * 8), "r"((uint32_t)BIG) : "memory");
                bulk_ld(smB + s * BIG, slab_src(s), FULL + s * 8);
            }
        }
        __syncwarp();

        uint32_t fmask = 0, emask = 0;
        int dfph = 0;
        #pragma unroll 1
        for (int ub = 0; ub < total; ++ub) {
            const int j = ub / 3, b3 = ub - j * 3, slot = ub & 3, db = j & 1;
            if (ub >= 2 && (ub + 2) < total) {
                const int sp = (ub - 2) & 3;
                mbar_wait(EMPTY + sp * 8, (emask >> sp) & 1u); emask ^= 1u << sp;
                if (elect_one()) {
                    asm volatile("mbarrier.arrive.expect_tx.shared.b64 _, [%0], %1;"
                                 :: "r"(FULL + sp * 8), "r"((uint32_t)BIG) : "memory");
                    bulk_ld(smB + sp * BIG, slab_src(ub + 2), FULL + sp * 8);
                }
                __syncwarp();
            }
            if (b3 == 0 && j >= 2) {
                mbar_wait(DFREE + db * 8, (uint32_t)((dfph >> db) & 1)); dfph ^= 1 << db;
            }
            mbar_wait(FULL + slot * 8, (fmask >> slot) & 1u); fmask ^= 1u << slot;
            if (elect_one()) {
                const uint32_t dcol = tmem + (uint32_t)(db * 64);
                #pragma unroll
                for (int c = 0; c < 4; ++c) {
                    const uint64_t bd = DESC_BASE |
                        (((smB + slot * BIG + c * SLAB) >> 4) & 0x3FFFu);
                    const int kg = b3 * 4 + c;
                    #pragma unroll
                    for (int kk = 0; kk < 4; ++kk) {
                        const uint32_t en = (kg > 0 || kk > 0) ? 1u : 0u;
                        const uint32_t at = tmem + 128u + (uint32_t)(kg * 32 + kk * 8);
                        asm volatile(
                            "{\n\t.reg .pred p;\n\tsetp.ne.u32 p, %4, 0;\n\t"
                            "tcgen05.mma.cta_group::1.kind::f16 [%0], [%1], %2, %3, "
                            "{%5,%5,%5,%5}, p;\n\t}"
                            :: "r"(dcol), "r"(at), "l"(bd + kk * 2),
                               "r"(IDESC), "r"(en), "r"(0u) : "memory");
                    }
                }
                asm volatile(
                    "tcgen05.commit.cta_group::1.mbarrier::arrive::one.shared::cluster.b64 [%0];"
                    :: "r"(EMPTY + slot * 8) : "memory");
                if (b3 == 2)
                    asm volatile(
                        "tcgen05.commit.cta_group::1.mbarrier::arrive::one.shared::cluster.b64 [%0];"
                        :: "r"(TDONE + db * 8) : "memory");
            }
            __syncwarp();
        }
        #pragma unroll 1
        for (int j = (ntc >= 2 ? ntc - 2 : 0); j < ntc; ++j) {
            const int db = j & 1;
            mbar_wait(DFREE + db * 8, (uint32_t)((dfph >> db) & 1)); dfph ^= 1 << db;
        }
        asm volatile("tcgen05.dealloc.cta_group::1.sync.aligned.b32 %0, %1;"
                     :: "r"(tmem), "r"(512u));
    } else {
        // ========== epilogue warps (1..16), two de-phased groups of 8 ==========
        const int e    = warp - 1;             // 0..15
        const int g    = e >> 3;               // group 0 -> even tiles, 1 -> odd
        const int lt   = (tid - 32) - g * 256; // 0..255 within group
        const int sub  = e & 3;                // subpartition (2 warps per sub/group)
        const int chb  = ((e >> 2) & 1) * 32;  // 32-col half of the 64-col D buffer
        const int lrow = sub * 32 + lane;
        const int rg   = mt * 128 + lrow;
        float* const Pbuf = Psm0 + (g << 13);  // group-private 32 KB buffer
        const int barid = 2 + g;
        int tdph = 0;
        float s1 = 0.f, s2 = 0.f, s3 = 0.f;

        #pragma unroll 1
        for (int j = g; j < ntc; j += 2) {
            // group barrier A: all group warps finished consuming Pbuf (iter j-2)
            asm volatile("bar.sync %0, 256;" :: "r"(barid) : "memory");
            // stage this group's P tile (coalesced LDG -> swizzled STS)
            {
                const int vb = (grp + NGRP * j) * 64;
                #pragma unroll
                for (int i = 0; i < 32; ++i) {
                    const int idx = lt + i * 256;
                    const int row = idx >> 6, col = idx & 63;
                    const int v = vb + col;
                    const float val = (v < V_SIZE)
                        ? __ldg(P + (size_t)(mt * 128 + row) * V_SIZE + v) : 0.f;
                    Pbuf[(row << 6) + (((col >> 2) ^ (row & 15)) << 2) + (col & 3)] = val;
                }
            }
            // group barrier B: STS drained, Pbuf fully written
            asm volatile("bar.sync %0, 256;" :: "r"(barid) : "memory");

            mbar_wait(TDONE + g * 8, (uint32_t)tdph); tdph ^= 1;
            asm volatile("tcgen05.fence::after_thread_sync;" ::: "memory");

            uint32_t d[32];
            const uint32_t ta = tmem + (uint32_t)(g * 64 + chb);
            asm volatile(
                "tcgen05.ld.sync.aligned.32x32b.x32.b32 "
                "{%0,%1,%2,%3,%4,%5,%6,%7,%8,%9,%10,%11,%12,%13,%14,%15,"
                "%16,%17,%18,%19,%20,%21,%22,%23,%24,%25,%26,%27,%28,%29,%30,%31}, [%32];"
                : "=r"(d[0]),  "=r"(d[1]),  "=r"(d[2]),  "=r"(d[3]),
                  "=r"(d[4]),  "=r"(d[5]),  "=r"(d[6]),  "=r"(d[7]),
                  "=r"(d[8]),  "=r"(d[9]),  "=r"(d[10]), "=r"(d[11]),
                  "=r"(d[12]), "=r"(d[13]), "=r"(d[14]), "=r"(d[15]),
                  "=r"(d[16]), "=r"(d[17]), "=r"(d[18]), "=r"(d[19]),
                  "=r"(d[20]), "=r"(d[21]), "=r"(d[22]), "=r"(d[23]),
                  "=r"(d[24]), "=r"(d[25]), "=r"(d[26]), "=r"(d[27]),
                  "=r"(d[28]), "=r"(d[29]), "=r"(d[30]), "=r"(d[31])
                : "r"(ta));
            asm volatile("tcgen05.wait::ld.sync.aligned;" ::: "memory");
            if (lane == 0) mbar_arrive(DFREE + g * 8);   // D buffer g released

            const float4* Psm4 = (const float4*)Pbuf;
            #pragma unroll
            for (int ii = 0; ii < 8; ++ii) {
                const int c4 = (chb >> 2) + ii;
                const float4 p4 = Psm4[(lrow << 4) + (c4 ^ (lrow & 15))];
                const float pv[4] = {p4.x, p4.y, p4.z, p4.w};
                #pragma unroll
                for (int ee = 0; ee < 4; ++ee) {
                    const float lg = __uint_as_float(d[ii * 4 + ee]);
                    s1 += exp2f(fmaf(lg, LOG2E, -LOG2E));
                    s2 = fmaf(pv[ee], lg, s2);
                    s3 = fmaf(pv[ee], __logf(fmaxf(pv[ee], 1e-12f)), s3);
                }
            }
        }
        atomicAdd(&g_S1[rg], s1);
        atomicAdd(&g_S2[rg], s2);
        atomicAdd(&g_S3[rg], s3);
    }
#else
    // Dead-code fallback (sm_103a cubin is always selected at runtime).
    for (int j = 0; j < ntc; ++j) {
        const int nt = grp + NGRP * j;
        for (int idx = tid; idx < 64 * 128; idx += NTHREADS) {
            const int row = idx >> 6, col = idx & 63;
            const int v = nt * 64 + col;
            if (v >= V_SIZE) continue;
            const int r = mt * 128 + row;
            float lg = 0.f;
            const __nv_bfloat16* ua = g_Un + (size_t)r * KDIM;
            const char* base = (const char*)g_Wn;
            for (int k = 0; k < KDIM; ++k) {
                const int kt = k >> 6, ek = k & 63;
                const uint32_t off = (uint32_t)(col * 128 + ek * 2);
                const uint32_t sw  = off ^ ((off >> 3) & 0x70u);
                const __nv_bfloat16 wb =
                    *(const __nv_bfloat16*)(base + (size_t)(nt * 12 + kt) * SLAB + sw);
                lg = fmaf(__bfloat162float(ua[k]), __bfloat162float(wb), lg);
            }
            const float p = __ldg(P + (size_t)r * V_SIZE + v);
            atomicAdd(&g_S1[r], exp2f(fmaf(lg, LOG2E, -LOG2E)) + PADC / 128.f);
            atomicAdd(&g_S2[r], p * lg);
            atomicAdd(&g_S3[r], p * __logf(fmaxf(p, 1e-12f)));
        }
    }
#endif
}

__global__ __launch_bounds__(1024) void finalize_kernel(const float* __restrict__ TE,
                                                        float* __restrict__ out) {
    const int t = threadIdx.x;
    float v0 = 0.f, v1 = 0.f, v2 = 0.f, v3 = 0.f, v4 = 0.f;
    for (int r = t; r < MROWS; r += 1024) {
        v0 += g_S3[r] - g_S2[r] + 1.f + __logf(g_S1[r] - PADC);  // remove padded cols
        float rr = g_rs[r];
        v1 += rr;
        float Hn = fminf(fmaxf(TE[r] * (1.f / LOG_V), 0.f), 1.f);
        float rtg = 3.0f / (1.f + expf(Hn));
        float d = rr - rtg;
        v2 = fmaf(d, d, v2);
        v3 += rtg;
        v4 += Hn;
    }
    #pragma unroll
    for (int o = 16; o > 0; o >>= 1) {
        v0 += __shfl_xor_sync(0xffffffffu, v0, o);
        v1 += __shfl_xor_sync(0xffffffffu, v1, o);
        v2 += __shfl_xor_sync(0xffffffffu, v2, o);
        v3 += __shfl_xor_sync(0xffffffffu, v3, o);
        v4 += __shfl_xor_sync(0xffffffffu, v4, o);
    }
    __shared__ float sb[32][5];
    if ((t & 31) == 0) {
        int w = t >> 5;
        sb[w][0] = v0; sb[w][1] = v1; sb[w][2] = v2; sb[w][3] = v3; sb[w][4] = v4;
    }
    __syncthreads();
    if (t < 32) {
        float u0 = sb[t][0], u1 = sb[t][1], u2 = sb[t][2], u3 = sb[t][3], u4 = sb[t][4];
        #pragma unroll
        for (int o = 16; o > 0; o >>= 1) {
            u0 += __shfl_xor_sync(0xffffffffu, u0, o);
            u1 += __shfl_xor_sync(0xffffffffu, u1, o);
            u2 += __shfl_xor_sync(0xffffffffu, u2, o);
            u3 += __shfl_xor_sync(0xffffffffu, u3, o);
            u4 += __shfl_xor_sync(0xffffffffu, u4, o);
        }
        if (t == 0) {
            const float inv = 1.f / (float)MROWS;
            float l_ang = u0 * inv;
            float l_rad = u2 * inv;
            out[0] = l_ang + 0.1f * l_rad;
            out[1] = l_ang;
            out[2] = l_rad;
            out[3] = u1 * inv;
            out[4] = u3 * inv;
            out[5] = u4 * inv;
        }
    }
}

extern "C" void kernel_launch(void* const* d_in, const int* in_sizes, int n_in,
                              void* d_out, int out_size) {
    const float* h  = (const float*)d_in[0];
    const float* W  = (const float*)d_in[1];
    const float* P  = (const float*)d_in[2];
    const float* TE = (const float*)d_in[3];
    float* out = (float*)d_out;

    cudaFuncSetAttribute(gemm_fused_kernel,
                         cudaFuncAttributeMaxDynamicSharedMemorySize, DYN_SMEM);

    prep_w_kernel<<<NP / 8, 256>>>(W);
    prep_s_kernel<<<MROWS / 8, 256>>>(h);
    transpose_a_kernel<<<dim3(16, 12), 128>>>();
    gemm_fused_kernel<<<dim3(16, NGRP), NTHREADS, DYN_SMEM>>>(P);
    finalize_kernel<<<1, 1024>>>(TE, out);
}